// round 6
// baseline (speedup 1.0000x reference)
#include <cuda_runtime.h>

#define BB   4
#define HH   256
#define WW   256
#define CC   32
#define KF   5
#define NTAP 25

#define TW   16                 // tile width (px)
#define TH   16                 // tile height (2 rows per warp, 8 warps)
#define TSS  260                // float stride per tap row (16B-aligned, pad)
#define SMEM_BYTES (NTAP * TSS * 4)   // 26000 B (scalar taps)

typedef unsigned long long u64;

__device__ __forceinline__ void fma2(u64& d, u64 a, u64 b) {
    asm("fma.rn.f32x2 %0, %1, %2, %0;" : "+l"(d) : "l"(a), "l"(b));
}
__device__ __forceinline__ u64 splat(float v) {
    u64 r;
    asm("mov.b64 %0, {%1, %1};" : "=l"(r) : "f"(v));
    return r;
}

// accumulate one (feat-row window, out-row) pair:
// acc[8] = 4 px x 4 ch; W[16] = 8 cols x 4 ch; taps scalar [25][TSS]
__device__ __forceinline__ void accum(u64* __restrict__ acc,
                                      const u64* __restrict__ W,
                                      const float* __restrict__ ts,
                                      int irow, int pixbase)
{
    #pragma unroll
    for (int j = 0; j < KF; j++) {
        const float4 t4 = *(const float4*)(ts + (irow * KF + j) * TSS + pixbase);
        const u64 t0 = splat(t4.x);
        const u64 t1 = splat(t4.y);
        const u64 t2 = splat(t4.z);
        const u64 t3 = splat(t4.w);
        fma2(acc[0], W[2*(0+j)+0], t0);
        fma2(acc[1], W[2*(0+j)+1], t0);
        fma2(acc[2], W[2*(1+j)+0], t1);
        fma2(acc[3], W[2*(1+j)+1], t1);
        fma2(acc[4], W[2*(2+j)+0], t2);
        fma2(acc[5], W[2*(2+j)+1], t2);
        fma2(acc[6], W[2*(3+j)+0], t3);
        fma2(acc[7], W[2*(3+j)+1], t3);
    }
}

__global__ void __launch_bounds__(256, 3)
kpc2d_kernel(const float* __restrict__ feat,
             const float* __restrict__ kern,
             const float* __restrict__ bias,
             float* __restrict__ out)
{
    extern __shared__ float ts[];   // [NTAP][TSS] scalar taps

    const int tid  = threadIdx.x;
    const int lane = tid & 31;
    const int wid  = tid >> 5;          // warp -> rows 2*wid, 2*wid+1
    const int cg   = lane >> 2;         // channel group (4 ch): ch 4cg..4cg+3
    const int pg   = lane & 3;          // pixel group (4 px): px 4pg..4pg+3
    const int w0   = blockIdx.x * TW;
    const int h0   = blockIdx.y * TH;
    const int bz   = blockIdx.z;

    // ---- tap fill: LDG.128, magic-divide, scalar transposed STS ----
    // per tile row: TW*NTAP = 400 floats = 100 float4; 16 rows -> 1600 float4
    const float4* kern4 = (const float4*)kern;
    #pragma unroll 1
    for (unsigned idx4 = tid; idx4 < TH * TW * NTAP / 4; idx4 += 256) {
        const unsigned row = idx4 / 100u;
        const unsigned k4  = (idx4 - row * 100u) * 4u;   // 0..396
        const size_t fidx = ((size_t)((bz * HH + h0 + (int)row) * WW + w0)) * NTAP + k4;
        const float4 v = __ldg(kern4 + (fidx >> 2));
        unsigned col = (k4 * 1311u) >> 15;               // k4/25 for k4<400
        unsigned tap = k4 - col * 25u;
        const unsigned pb = row * TW;
        float vv[4] = {v.x, v.y, v.z, v.w};
        #pragma unroll
        for (int e = 0; e < 4; e++) {
            ts[tap * TSS + pb + col] = vv[e];
            if (++tap == 25u) { tap = 0u; col++; }
        }
    }

    // bias for this thread's 4 channels -> 2 u64
    const ulonglong2 bv = *(const ulonglong2*)(bias + 4 * cg);
    __syncthreads();

    // ---- compute: warp = 2 rows x 16 px x 32 ch; thread = 2r x 4px x 4ch ----
    u64 a0[8], a1[8];
    #pragma unroll
    for (int p = 0; p < 4; p++) {
        a0[2*p] = bv.x; a0[2*p+1] = bv.y;
        a1[2*p] = bv.x; a1[2*p+1] = bv.y;
    }

    const int r0    = wid * 2;
    const int pxb   = pg * 4;                 // thread's pixel base in tile row
    const int pix0  = r0 * TW + pxb;          // tap pixel index row0
    const int pix1  = pix0 + TW;
    const bool interior = (h0 >= 2) && (h0 + TH + 2 <= HH) &&
                          (w0 >= 2) && (w0 + TW + 2 <= WW);

    if (interior) {
        #pragma unroll
        for (int g = 0; g < 6; g++) {
            const int gh = h0 + r0 + g - 2;
            // window: 8 cols x 4 ch, one LDG.128 per col
            const char* frow = (const char*)
                (feat + ((size_t)((bz * HH + gh) * WW + (w0 + pxb - 2))) * CC + 4 * cg);
            u64 W[16];
            #pragma unroll
            for (int c = 0; c < 8; c++) {
                const ulonglong2 f = __ldg((const ulonglong2*)(frow + c * (CC * 4)));
                W[2*c] = f.x; W[2*c+1] = f.y;
            }
            if (g < 5) accum(a0, W, ts, g,     pix0);
            if (g > 0) accum(a1, W, ts, g - 1, pix1);
        }
    } else {
        #pragma unroll 1
        for (int g = 0; g < 6; g++) {
            const int gh = h0 + r0 + g - 2;
            const bool rok = (unsigned)gh < HH;
            const char* frow = (const char*)
                (feat + ((size_t)((bz * HH + gh) * WW + (w0 + pxb - 2))) * CC + 4 * cg);
            u64 W[16];
            #pragma unroll
            for (int c = 0; c < 8; c++) {
                const int gw = w0 + pxb + c - 2;
                if (rok && (unsigned)gw < WW) {
                    const ulonglong2 f = __ldg((const ulonglong2*)(frow + c * (CC * 4)));
                    W[2*c] = f.x; W[2*c+1] = f.y;
                } else {
                    W[2*c] = 0ULL; W[2*c+1] = 0ULL;
                }
            }
            if (g < 5) accum(a0, W, ts, g,     pix0);
            if (g > 0) accum(a1, W, ts, g - 1, pix1);
        }
    }

    // ---- store: 2 rows x 4 px, one STG.128 (4 ch) each ----
    char* o0 = (char*)
        (out + ((size_t)((bz * HH + h0 + r0) * WW + (w0 + pxb))) * CC + 4 * cg);
    char* o1 = o0 + (size_t)WW * CC * 4;
    #pragma unroll
    for (int p = 0; p < 4; p++) {
        ulonglong2 v0; v0.x = a0[2*p]; v0.y = a0[2*p+1];
        ulonglong2 v1; v1.x = a1[2*p]; v1.y = a1[2*p+1];
        *(ulonglong2*)(o0 + p * (CC * 4)) = v0;
        *(ulonglong2*)(o1 + p * (CC * 4)) = v1;
    }
}

extern "C" void kernel_launch(void* const* d_in, const int* in_sizes, int n_in,
                              void* d_out, int out_size)
{
    const float* feat = (const float*)d_in[0];
    const float* kern = (const float*)d_in[1];
    const float* bias = (const float*)d_in[2];
    float* out = (float*)d_out;

    static bool attr_set = false;
    if (!attr_set) {
        cudaFuncSetAttribute(kpc2d_kernel,
                             cudaFuncAttributeMaxDynamicSharedMemorySize,
                             SMEM_BYTES);
        attr_set = true;
    }

    dim3 grid(WW / TW, HH / TH, BB);   // 16 x 16 x 4 = 1024 blocks
    kpc2d_kernel<<<grid, 256, SMEM_BYTES>>>(feat, kern, bias, out);
}